// round 4
// baseline (speedup 1.0000x reference)
#include <cuda_runtime.h>
#include <stdint.h>

// Shapes fixed by the dataset
#define B_   32
#define C_   4
#define H_   512
#define W_   512
#define T_   64
#define NTOT (B_ * C_ * H_ * W_)          // 33,554,432 elements
#define V_   (NTOT / 4)                   // 8,388,608 float4 pairs
#define CH_STRIDE (H_ * W_)               // 262,144

#define CORR_BLOCKS   128                 // 4 strips x 32 batches
#define STREAM_BLOCKS 4096
#define TOTAL_BLOCKS  (CORR_BLOCKS + STREAM_BLOCKS)
#define THREADS       256
#define STRIDE_V      (STREAM_BLOCKS * THREADS)   // 1<<20
#define ITERS         (V_ / STRIDE_V)             // 8

__device__ double g_acc;          // zero-init; reset by last block each run
__device__ unsigned int g_count;  // zero-init; reset by last block each run

__global__ __launch_bounds__(THREADS)
void fused_loss_kernel(const float* __restrict__ pred,
                       const float* __restrict__ targ,
                       const float* __restrict__ pos,   // [B,T,2]
                       float* __restrict__ out) {
    const int bid = blockIdx.x;
    const int tid = threadIdx.x;

    __shared__ float warp_sums[THREADS / 32];
    __shared__ unsigned int bitmap[128][16];   // 128-row strip x 512 bits (corr only)
    __shared__ float2 spos[T_];                // (corr only)

    float acc = 0.0f;        // this block's contribution to the global sum
    float scale = 1.0f;      // corr blocks contribute 3x their masked sum

    if (bid >= CORR_BLOCKS) {
        // ================= streaming path: pure HBM-bound SSE =================
        const int tg = (bid - CORR_BLOCKS) * THREADS + tid;
        const float4* __restrict__ p4 = reinterpret_cast<const float4*>(pred);
        const float4* __restrict__ t4 = reinterpret_cast<const float4*>(targ);
#pragma unroll
        for (int i = 0; i < ITERS; i++) {
            const int v = tg + i * STRIDE_V;     // always < V_
            const float4 p = p4[v];
            const float4 t = t4[v];
            const float d0 = p.x - t.x;
            const float d1 = p.y - t.y;
            const float d2 = p.z - t.z;
            const float d3 = p.w - t.w;
            acc = fmaf(d0, d0, acc);
            acc = fmaf(d1, d1, acc);
            acc = fmaf(d2, d2, acc);
            acc = fmaf(d3, d3, acc);
        }
    } else {
        // ================= correction path: 3 * masked-pixel SSE ==============
        scale = 3.0f;
        const int b  = bid >> 2;                 // batch
        const int r0 = (bid & 3) << 7;           // strip start row

        // zero bitmap, load this batch's positions
#pragma unroll
        for (int k = 0; k < 8; k++)
            (&bitmap[0][0])[k * THREADS + tid] = 0u;
        if (tid < T_)
            spos[tid] = reinterpret_cast<const float2*>(pos)[b * T_ + tid];
        __syncthreads();

        // paint boxes: 4 threads per token, each covers rows j, j+4, j+8
        {
            const int tok = tid >> 2;
            const int sub = tid & 3;
            const float x = spos[tok].x;
            const float y = spos[tok].y;
            if (x > 0.0f && y > 0.0f) {
                const int yp = (int)floorf(y * (float)H_);
                const int xp = (int)floorf(x * (float)W_);
                int x0 = xp - 5; if (x0 < 0) x0 = 0;
                int x1 = xp + 5; if (x1 > W_) x1 = W_;
                if (x0 < x1) {
                    const int w0 = x0 >> 5;
                    const int w1 = (x1 - 1) >> 5;
                    unsigned int m0, m1;
                    if (w0 == w1) {
                        m0 = ((1u << (x1 - x0)) - 1u) << (x0 & 31);
                        m1 = 0u;
                    } else {
                        m0 = 0xFFFFFFFFu << (x0 & 31);
                        m1 = (1u << (x1 & 31)) - 1u;
                    }
#pragma unroll
                    for (int j = 0; j < 3; j++) {
                        const int jr = sub + 4 * j;          // 0..11
                        const int h  = yp - 5 + jr;
                        if (jr < 10 && h >= r0 && h < r0 + 128 && h >= 0 && h < H_) {
                            const int lr = h - r0;
                            atomicOr(&bitmap[lr][w0], m0);
                            if (m1) atomicOr(&bitmap[lr][w1], m1);
                        }
                    }
                }
            }
        }
        __syncthreads();

        // scan set bits, gather diff^2 over 4 channels
        const float* __restrict__ pb = pred + (size_t)b * C_ * CH_STRIDE;
        const float* __restrict__ tb = targ + (size_t)b * C_ * CH_STRIDE;
#pragma unroll
        for (int k = 0; k < 8; k++) {
            const int w = k * THREADS + tid;
            unsigned int word = bitmap[w >> 4][w & 15];
            const int h = r0 + (w >> 4);
            const int colbase = (w & 15) << 5;
            while (word) {
                const int bit = __ffs(word) - 1;
                word &= word - 1u;
                const int idx = h * W_ + colbase + bit;
#pragma unroll
                for (int c = 0; c < C_; c++) {
                    const float d = pb[c * CH_STRIDE + idx] - tb[c * CH_STRIDE + idx];
                    acc = fmaf(d, d, acc);
                }
            }
        }
    }

    // ================= block reduction + global accumulate ====================
#pragma unroll
    for (int off = 16; off > 0; off >>= 1)
        acc += __shfl_xor_sync(0xFFFFFFFFu, acc, off);

    const int lane = tid & 31;
    const int wid  = tid >> 5;
    if (lane == 0) warp_sums[wid] = acc;
    __syncthreads();

    if (tid == 0) {
        float s = 0.0f;
#pragma unroll
        for (int wj = 0; wj < THREADS / 32; wj++) s += warp_sums[wj];
        atomicAdd(&g_acc, (double)(s * scale));

        __threadfence();
        const unsigned int ticket = atomicAdd(&g_count, 1u);
        if (ticket == TOTAL_BLOCKS - 1) {
            __threadfence();
            const double total = g_acc;
            out[0] = (float)(total * (1.0 / (double)NTOT));
            g_acc   = 0.0;   // restore invariant for next graph replay
            g_count = 0u;
        }
    }
}

extern "C" void kernel_launch(void* const* d_in, const int* in_sizes, int n_in,
                              void* d_out, int out_size) {
    const float* pred = (const float*)d_in[0];   // predicted_noise [B,C,H,W] f32
    const float* targ = (const float*)d_in[1];   // target_noise    [B,C,H,W] f32
    // d_in[2] = text_tokens (int64) — mathematically unused
    const float* pos  = (const float*)d_in[3];   // text_positions [B,T,2] f32
    float* out = (float*)d_out;

    fused_loss_kernel<<<TOTAL_BLOCKS, THREADS>>>(pred, targ, pos, out);
}